// round 14
// baseline (speedup 1.0000x reference)
#include <cuda_runtime.h>
#include <cuda_bf16.h>
#include <cstdint>

// Problem constants
#define Nn 4
#define Pp 2048
#define Dd 512
#define Hh 8
#define HDv 64
#define NHv (Nn*Hh)              // 32
#define ROWSv (Nn*Pp*Hh)         // 65536
#define SCALE 0.04419417382415922f   // 1/sqrt(512)

// ---------------------------------------------------------------------------
// Device scratch (no allocations allowed)
// ---------------------------------------------------------------------------
static __device__ __nv_bfloat16 g_qh[Nn*Pp*Dd];     // Q hi  [nh][p][64]
static __device__ __nv_bfloat16 g_ql[Nn*Pp*Dd];     // Q lo
static __device__ __nv_bfloat16 g_kh[Nn*Pp*Dd];     // K hi
static __device__ __nv_bfloat16 g_kl[Nn*Pp*Dd];     // K lo
static __device__ __nv_bfloat16 g_vTh[Nn*Pp*Dd];    // V^T hi [nh][e=64][p=2048]
static __device__ __nv_bfloat16 g_vTl[Nn*Pp*Dd];    // V^T lo
static __device__ uint32_t g_oh[Nn*Pp*Dd/2];        // O hi, bf16x2 [row(8192)][256]
static __device__ uint32_t g_ol[Nn*Pp*Dd/2];        // O lo
static __device__ float g_rowmax[ROWSv];
static __device__ float g_rowinv[ROWSv];
static __device__ float g_attn_scratch[NHv*Pp*Pp];   // fallback
static __device__ float g_out_scratch[Nn*Pp*Dd];     // fallback

// ---------------------------------------------------------------------------
// PTX helpers
// ---------------------------------------------------------------------------
__device__ __forceinline__ uint32_t s2u(const void* p) {
    uint32_t a;
    asm("{ .reg .u64 t; cvta.to.shared.u64 t, %1; cvt.u32.u64 %0, t; }"
        : "=r"(a) : "l"(p));
    return a;
}

__device__ __forceinline__ void mma_bf16(float* c, const uint32_t* a,
                                         const uint32_t* b) {
    asm volatile(
        "mma.sync.aligned.m16n8k16.row.col.f32.bf16.bf16.f32 "
        "{%0,%1,%2,%3}, {%4,%5,%6,%7}, {%8,%9}, {%0,%1,%2,%3};"
        : "+f"(c[0]), "+f"(c[1]), "+f"(c[2]), "+f"(c[3])
        : "r"(a[0]), "r"(a[1]), "r"(a[2]), "r"(a[3]),
          "r"(b[0]), "r"(b[1]));
}

__device__ __forceinline__ void ldsm_x4(uint32_t* r, uint32_t addr) {
    asm volatile(
        "ldmatrix.sync.aligned.m8n8.x4.shared.b16 {%0,%1,%2,%3}, [%4];"
        : "=r"(r[0]), "=r"(r[1]), "=r"(r[2]), "=r"(r[3]) : "r"(addr));
}

__device__ __forceinline__ void cpa16(uint32_t saddr, const void* gaddr) {
    asm volatile("cp.async.ca.shared.global [%0], [%1], 16;"
                 :: "r"(saddr), "l"(gaddr) : "memory");
}
#define CPA_COMMIT() asm volatile("cp.async.commit_group;" ::: "memory")
#define CPA_WAIT0()  asm volatile("cp.async.wait_group 0;" ::: "memory")
#define CPA_WAIT1()  asm volatile("cp.async.wait_group 1;" ::: "memory")

__device__ __forceinline__ uint32_t pack2bf(float a, float b) {
    __nv_bfloat162 t = __floats2bfloat162_rn(a, b);
    return *reinterpret_cast<uint32_t*>(&t);
}
__device__ __forceinline__ void packhilo(float a, float b,
                                         uint32_t& hi, uint32_t& lo) {
    float ha = __bfloat162float(__float2bfloat16_rn(a));
    float hb = __bfloat162float(__float2bfloat16_rn(b));
    hi = pack2bf(a, b);
    lo = pack2bf(a - ha, b - hb);
}
__device__ __forceinline__ void split4(float x0, float x1, float x2, float x3,
                                       uint2& hi, uint2& lo) {
    packhilo(x0, x1, hi.x, lo.x);
    packhilo(x2, x3, hi.y, lo.y);
}

#define FMA16(acc, a, b)                                     \
  acc[0][0] += a.x*b.x; acc[0][1] += a.x*b.y;                \
  acc[0][2] += a.x*b.z; acc[0][3] += a.x*b.w;                \
  acc[1][0] += a.y*b.x; acc[1][1] += a.y*b.y;                \
  acc[1][2] += a.y*b.z; acc[1][3] += a.y*b.w;                \
  acc[2][0] += a.z*b.x; acc[2][1] += a.z*b.y;                \
  acc[2][2] += a.z*b.z; acc[2][3] += a.z*b.w;                \
  acc[3][0] += a.w*b.x; acc[3][1] += a.w*b.y;                \
  acc[3][2] += a.w*b.z; acc[3][3] += a.w*b.w;

// ---------------------------------------------------------------------------
// K1: QKV projection (FFMA) -> bf16 hi/lo outputs; V transposed.
// ---------------------------------------------------------------------------
__global__ __launch_bounds__(256) void k_qkv(
    const float* __restrict__ x,
    const float* __restrict__ Wq, const float* __restrict__ Wk,
    const float* __restrict__ Wv)
{
    __shared__ __align__(16) float Xst[64][68];
    __shared__ __align__(16) float Wt[64][68];
    const int r0  = blockIdx.x * 64;
    const int tid = threadIdx.x;

    for (int i = tid; i < 4096; i += 256) {
        int r = i >> 6, d = i & 63;
        Xst[d][r] = x[(size_t)(r0 + r) * 64 + d];
    }

    const int tx = tid & 15, ty = tid >> 4;
    const float* Ws[3] = {Wq, Wk, Wv};

    for (int m = 0; m < 3; m++) {
        __syncthreads();
        for (int i = tid; i < 4096; i += 256) {
            int e = i >> 6, d = i & 63;
            Wt[d][e] = Ws[m][i];
        }
        __syncthreads();

        float acc[4][4] = {};
        #pragma unroll 8
        for (int d = 0; d < 64; d++) {
            float4 a = *(const float4*)&Xst[d][ty * 4];
            float4 b = *(const float4*)&Wt[d][tx * 4];
            FMA16(acc, a, b);
        }

        if (m < 2) {
            __nv_bfloat16* Gh = (m == 0) ? g_qh : g_kh;
            __nv_bfloat16* Gl = (m == 0) ? g_ql : g_kl;
            #pragma unroll
            for (int i2 = 0; i2 < 4; i2++) {
                int r = r0 + ty * 4 + i2;
                int h = r & 7; int np = r >> 3;
                int p = np & 2047; int n_ = np >> 11;
                size_t dst = ((size_t)((n_ * 8 + h) * 2048 + p)) * 64 + tx * 4;
                uint2 hi, lo;
                split4(acc[i2][0], acc[i2][1], acc[i2][2], acc[i2][3], hi, lo);
                *(uint2*)&Gh[dst] = hi;
                *(uint2*)&Gl[dst] = lo;
            }
        } else {
            __syncthreads();
            #pragma unroll
            for (int i2 = 0; i2 < 4; i2++)
                #pragma unroll
                for (int j = 0; j < 4; j++)
                    Xst[tx * 4 + j][ty * 4 + i2] = acc[i2][j];
            __syncthreads();

            int np0 = r0 >> 3;
            int n_ = np0 >> 11;
            int p0 = np0 & 2047;
            #pragma unroll
            for (int pr = 0; pr < 2; pr++) {
                int pair = tid + pr * 256;       // (h, e)
                int h = pair >> 6, e = pair & 63;
                float v[8];
                #pragma unroll
                for (int pi = 0; pi < 8; pi++) v[pi] = Xst[e][pi * 8 + h];
                uint2 hi0, lo0, hi1, lo1;
                split4(v[0], v[1], v[2], v[3], hi0, lo0);
                split4(v[4], v[5], v[6], v[7], hi1, lo1);
                uint4 hi4 = make_uint4(hi0.x, hi0.y, hi1.x, hi1.y);
                uint4 lo4 = make_uint4(lo0.x, lo0.y, lo1.x, lo1.y);
                size_t base = ((size_t)((n_ * 8 + h) * 64 + e)) * 2048 + p0;
                *(uint4*)&g_vTh[base] = hi4;
                *(uint4*)&g_vTl[base] = lo4;
            }
        }
    }
}

// ---------------------------------------------------------------------------
// K2: E = scale*Q@K^T (split bf16 MMA): writes RAW E to attn buffer + online
// softmax stats. grid = (qb=16, nh=32), 256 threads, 2 blocks/SM, cp.async x2.
// ---------------------------------------------------------------------------
#define STATS_STG 36864
__global__ __launch_bounds__(256, 2) void k_stats_tc(float* __restrict__ attn)
{
    extern __shared__ __align__(16) char dynsm[];
    const uint32_t smb = s2u(dynsm);

    const int tid = threadIdx.x;
    const int w = tid >> 5, lane = tid & 31;
    const int qb = blockIdx.x, nh = blockIdx.y;
    const int q0 = qb * 128;

    uint32_t aqh[16], aql[16];
    {
        const uint32_t* qhp = (const uint32_t*)g_qh;
        const uint32_t* qlp = (const uint32_t*)g_ql;
        int qrow = nh * 2048 + q0 + w * 16;
        #pragma unroll
        for (int dc = 0; dc < 4; dc++)
            #pragma unroll
            for (int r = 0; r < 4; r++) {
                int row = qrow + (lane >> 2) + 8 * (r & 1);
                int col2 = dc * 8 + (lane & 3) + 4 * (r >> 1);
                aqh[dc * 4 + r] = qhp[(size_t)row * 32 + col2];
                aql[dc * 4 + r] = qlp[(size_t)row * 32 + col2];
            }
    }

    const int r0g = nh * 2048 + q0 + w * 16 + (lane >> 2);
    float* arow0 = attn + (size_t)r0g * 2048;
    float* arow1 = attn + (size_t)(r0g + 8) * 2048;

    auto issue = [&](int st, int kc) {
        uint32_t sb = smb + st * STATS_STG;
        #pragma unroll
        for (int it = 0; it < 4; it++) {
            int idx = it * 256 + tid;
            int row = idx >> 3, c8 = idx & 7;
            uint32_t so = sb + (uint32_t)(row * 144 + c8 * 16);
            cpa16(so,         (const uint4*)g_kh + (size_t)(nh * 2048 + kc + row) * 8 + c8);
            cpa16(so + 18432, (const uint4*)g_kl + (size_t)(nh * 2048 + kc + row) * 8 + c8);
        }
    };

    float m0 = -1e30f, s0 = 0.f, m1 = -1e30f, s1 = 0.f;

    issue(0, 0);
    CPA_COMMIT();

    for (int ic = 0; ic < 16; ic++) {
        const int kc = ic * 128;
        if (ic + 1 < 16) {
            issue((ic + 1) & 1, kc + 128);
            CPA_COMMIT();
            CPA_WAIT1();
        } else {
            CPA_WAIT0();
        }
        __syncthreads();

        const char* khp = dynsm + (ic & 1) * STATS_STG;
        const char* klp = khp + 18432;

        #pragma unroll 4
        for (int n8 = 0; n8 < 16; n8++) {
            float c[4] = {0.f, 0.f, 0.f, 0.f};
            int tok = n8 * 8 + (lane >> 2);
            #pragma unroll
            for (int dc = 0; dc < 4; dc++) {
                int dcol = dc * 16 + (lane & 3) * 2;
                uint32_t bh[2], bl[2];
                bh[0] = *(const uint32_t*)(khp + tok * 144 + dcol * 2);
                bh[1] = *(const uint32_t*)(khp + tok * 144 + dcol * 2 + 16);
                bl[0] = *(const uint32_t*)(klp + tok * 144 + dcol * 2);
                bl[1] = *(const uint32_t*)(klp + tok * 144 + dcol * 2 + 16);
                mma_bf16(c, &aqh[dc * 4], bh);
                mma_bf16(c, &aqh[dc * 4], bl);
                mma_bf16(c, &aql[dc * 4], bh);
            }
            float e0 = c[0] * SCALE, e1 = c[1] * SCALE;
            float e2 = c[2] * SCALE, e3 = c[3] * SCALE;
            // store raw E (the normalize pass reads exactly these values)
            int col = kc + n8 * 8 + (lane & 3) * 2;
            *(float2*)&arow0[col] = make_float2(e0, e1);
            *(float2*)&arow1[col] = make_float2(e2, e3);
            float lm0 = fmaxf(e0, e1), lm1 = fmaxf(e2, e3);
            float nm0 = fmaxf(m0, lm0), nm1 = fmaxf(m1, lm1);
            s0 = s0 * __expf(m0 - nm0) + __expf(e0 - nm0) + __expf(e1 - nm0);
            s1 = s1 * __expf(m1 - nm1) + __expf(e2 - nm1) + __expf(e3 - nm1);
            m0 = nm0; m1 = nm1;
        }
        __syncthreads();
    }

    #pragma unroll
    for (int off = 1; off <= 2; off <<= 1) {
        float om = __shfl_xor_sync(0xFFFFFFFFu, m0, off);
        float os = __shfl_xor_sync(0xFFFFFFFFu, s0, off);
        float nm = fmaxf(m0, om);
        s0 = s0 * __expf(m0 - nm) + os * __expf(om - nm);
        m0 = nm;
        om = __shfl_xor_sync(0xFFFFFFFFu, m1, off);
        os = __shfl_xor_sync(0xFFFFFFFFu, s1, off);
        nm = fmaxf(m1, om);
        s1 = s1 * __expf(m1 - nm) + os * __expf(om - nm);
        m1 = nm;
    }
    if ((lane & 3) == 0) {
        int grow0 = nh * 2048 + q0 + w * 16 + (lane >> 2);
        g_rowmax[grow0] = m0;
        g_rowinv[grow0] = 1.0f / s0;
        g_rowmax[grow0 + 8] = m1;
        g_rowinv[grow0 + 8] = 1.0f / s1;
    }
}

// ---------------------------------------------------------------------------
// K3: read raw E, normalize -> overwrite attention with P; A@V (split MMA).
// grid = (qb=16, nh=32), 256 threads, 2 blocks/SM, cp.async 2-stage.
// Stage = E 128x64 f32 (pitch 272B, 16B-aligned rows) + Vh/Vl 64x64 bf16.
// ---------------------------------------------------------------------------
#define AV2_E   34816
#define AV2_STG 53248
__global__ __launch_bounds__(256, 2) void k_attnv_tc(float* __restrict__ attn)
{
    extern __shared__ __align__(16) char dynsm[];
    const uint32_t smb = s2u(dynsm);

    const int tid = threadIdx.x;
    const int w = tid >> 5, lane = tid & 31;
    const int qb = blockIdx.x, nh = blockIdx.y;
    const int q0 = qb * 128;
    const int n_ = nh >> 3, h = nh & 7;

    const int r0g = nh * 2048 + q0 + w * 16 + (lane >> 2);
    const float m0 = g_rowmax[r0g],     i0 = g_rowinv[r0g];
    const float m1 = g_rowmax[r0g + 8], i1 = g_rowinv[r0g + 8];

    float* arow0 = attn + (size_t)r0g * 2048;
    float* arow1 = attn + (size_t)(r0g + 8) * 2048;
    const float* Ebase = attn + (size_t)(nh * 2048 + q0) * 2048;

    auto issue = [&](int st, int kc) {
        uint32_t sb = smb + st * AV2_STG;
        // E chunk: 128 rows x 64 f32, smem pitch 272B (17 x 16B)
        #pragma unroll
        for (int it = 0; it < 8; it++) {
            int idx = it * 256 + tid;
            int r = idx >> 4, c4 = idx & 15;
            cpa16(sb + (uint32_t)(r * 272 + c4 * 16),
                  Ebase + (size_t)r * 2048 + kc + c4 * 4);
        }
        // V^T chunk hi/lo
        #pragma unroll
        for (int it = 0; it < 2; it++) {
            int idx = it * 256 + tid;
            int row = idx >> 3, c8 = idx & 7;
            uint32_t so = sb + AV2_E + (uint32_t)(row * 144 + c8 * 16);
            cpa16(so,        (const uint4*)g_vTh + (size_t)(nh * 64 + row) * 256 + (kc >> 3) + c8);
            cpa16(so + 9216, (const uint4*)g_vTl + (size_t)(nh * 64 + row) * 256 + (kc >> 3) + c8);
        }
    };

    float o[8][4];
    #pragma unroll
    for (int ne = 0; ne < 8; ne++)
        #pragma unroll
        for (int j = 0; j < 4; j++) o[ne][j] = 0.f;

    issue(0, 0);
    CPA_COMMIT();

    const int er0 = w * 16 + (lane >> 2);

    for (int ic = 0; ic < 32; ic++) {
        const int kc = ic * 64;
        if (ic + 1 < 32) {
            issue((ic + 1) & 1, kc + 64);
            CPA_COMMIT();
            CPA_WAIT1();
        } else {
            CPA_WAIT0();
        }
        __syncthreads();

        const char* ep  = dynsm + (ic & 1) * AV2_STG;
        const char* vhp = ep + AV2_E;
        const char* vlp = vhp + 9216;

        #pragma unroll
        for (int h2 = 0; h2 < 2; h2++) {
            uint32_t pah[8], pal[8];
            #pragma unroll
            for (int n8l = 0; n8l < 4; n8l++) {
                int n8 = h2 * 4 + n8l;
                int colf = n8 * 8 + (lane & 3) * 2;
                float2 e01 = *(const float2*)(ep + er0 * 272 + colf * 4);
                float2 e23 = *(const float2*)(ep + (er0 + 8) * 272 + colf * 4);
                float p0 = __expf(e01.x - m0) * i0;
                float p1 = __expf(e01.y - m0) * i0;
                float p2 = __expf(e23.x - m1) * i1;
                float p3 = __expf(e23.y - m1) * i1;
                int col = kc + colf;
                *(float2*)&arow0[col] = make_float2(p0, p1);
                *(float2*)&arow1[col] = make_float2(p2, p3);
                int base = (n8l >> 1) * 4 + (n8l & 1) * 2;
                packhilo(p0, p1, pah[base],     pal[base]);
                packhilo(p2, p3, pah[base + 1], pal[base + 1]);
            }

            #pragma unroll
            for (int kkl = 0; kkl < 2; kkl++) {
                int kk = h2 * 2 + kkl;
                #pragma unroll
                for (int ne = 0; ne < 8; ne++) {
                    int e = ne * 8 + (lane >> 2);
                    int tcol = kk * 16 + (lane & 3) * 2;
                    uint32_t bh[2], bl[2];
                    bh[0] = *(const uint32_t*)(vhp + e * 144 + tcol * 2);
                    bh[1] = *(const uint32_t*)(vhp + e * 144 + tcol * 2 + 16);
                    bl[0] = *(const uint32_t*)(vlp + e * 144 + tcol * 2);
                    bl[1] = *(const uint32_t*)(vlp + e * 144 + tcol * 2 + 16);
                    mma_bf16(o[ne], &pah[kkl * 4], bh);
                    mma_bf16(o[ne], &pah[kkl * 4], bl);
                    mma_bf16(o[ne], &pal[kkl * 4], bh);
                }
            }
        }
        __syncthreads();
    }

    // epilogue: O rows as bf16 hi/lo (row-major [8192][256] words)
    int row = n_ * 2048 + q0 + w * 16 + (lane >> 2);
    #pragma unroll
    for (int ne = 0; ne < 8; ne++) {
        int col2 = h * 32 + ne * 4 + (lane & 3);
        uint32_t hh, ll;
        packhilo(o[ne][0], o[ne][1], hh, ll);
        g_oh[(size_t)row * 256 + col2] = hh;
        g_ol[(size_t)row * 256 + col2] = ll;
        packhilo(o[ne][2], o[ne][3], hh, ll);
        g_oh[(size_t)(row + 8) * 256 + col2] = hh;
        g_ol[(size_t)(row + 8) * 256 + col2] = ll;
    }
}

// ---------------------------------------------------------------------------
// K4: out = O @ Wo^T + bo via split bf16 HMMA. 2 blocks/SM.
// grid = (cb=8, rb=64), 256 threads (8 warps, 16 r-rows each).
// ---------------------------------------------------------------------------
__global__ __launch_bounds__(256, 2) void k_oproj_tc(
    const float* __restrict__ Wo, const float* __restrict__ bo,
    float* __restrict__ out)
{
    __shared__ __align__(16) __nv_bfloat16 Wh[64][72];
    __shared__ __align__(16) __nv_bfloat16 Wl[64][72];

    const int tid = threadIdx.x;
    const int w = tid >> 5, lane = tid & 31;
    const int c0 = blockIdx.x * 64, r0 = blockIdx.y * 128;

    const uint32_t whb = s2u(&Wh[0][0]);
    const uint32_t wlb = s2u(&Wl[0][0]);
    const uint32_t lmoff = (uint32_t)((lane & 7) * 144 + (lane >> 3) * 16);

    float acc[8][4];
    #pragma unroll
    for (int n8 = 0; n8 < 8; n8++)
        #pragma unroll
        for (int j = 0; j < 4; j++) acc[n8][j] = 0.f;

    for (int cc = 0; cc < 8; cc++) {
        if (cc) __syncthreads();
        #pragma unroll
        for (int it = 0; it < 8; it++) {
            int pi = it * 256 + tid;
            int row = pi >> 5, cp = pi & 31;
            float2 w2 = *(const float2*)&Wo[(size_t)(c0 + row) * 512 + cc * 64 + cp * 2];
            uint32_t hh, ll;
            packhilo(w2.x, w2.y, hh, ll);
            *(uint32_t*)&Wh[row][cp * 2] = hh;
            *(uint32_t*)&Wl[row][cp * 2] = ll;
        }
        __syncthreads();

        uint32_t aoh[16], aol[16];
        int rrow = r0 + w * 16;
        #pragma unroll
        for (int dc = 0; dc < 4; dc++)
            #pragma unroll
            for (int r = 0; r < 4; r++) {
                int row = rrow + (lane >> 2) + 8 * (r & 1);
                int col2 = cc * 32 + dc * 8 + (lane & 3) + 4 * (r >> 1);
                aoh[dc * 4 + r] = g_oh[(size_t)row * 256 + col2];
                aol[dc * 4 + r] = g_ol[(size_t)row * 256 + col2];
            }

        #pragma unroll
        for (int n8 = 0; n8 < 8; n8++) {
            uint32_t bh[8], bl[8];
            uint32_t base = (uint32_t)(n8 * 1152) + lmoff;
            ldsm_x4(bh,     whb + base);
            ldsm_x4(bh + 4, whb + base + 64);
            ldsm_x4(bl,     wlb + base);
            ldsm_x4(bl + 4, wlb + base + 64);
            #pragma unroll
            for (int dc = 0; dc < 4; dc++) {
                mma_bf16(acc[n8], &aoh[dc * 4], &bh[dc * 2]);
                mma_bf16(acc[n8], &aoh[dc * 4], &bl[dc * 2]);
                mma_bf16(acc[n8], &aol[dc * 4], &bh[dc * 2]);
            }
        }
    }

    int row = r0 + w * 16 + (lane >> 2);
    #pragma unroll
    for (int n8 = 0; n8 < 8; n8++) {
        int c = c0 + n8 * 8 + (lane & 3) * 2;
        float2 bb = *(const float2*)&bo[c];
        *(float2*)&out[(size_t)row * 512 + c] =
            make_float2(acc[n8][0] + bb.x, acc[n8][1] + bb.y);
        *(float2*)&out[(size_t)(row + 8) * 512 + c] =
            make_float2(acc[n8][2] + bb.x, acc[n8][3] + bb.y);
    }
}

// ---------------------------------------------------------------------------
extern "C" void kernel_launch(void* const* d_in, const int* in_sizes, int n_in,
                              void* d_out, int out_size)
{
    const float* x  = (const float*)d_in[0];
    const float* Wq = (const float*)d_in[1];
    const float* Wk = (const float*)d_in[2];
    const float* Wv = (const float*)d_in[3];
    const float* Wo = (const float*)d_in[4];
    const float* bo = (const float*)d_in[5];

    const long long OUT_E = (long long)Nn * Pp * Dd;      // 4194304
    const long long ATT_E = (long long)NHv * Pp * Pp;     // 134217728
    const long long os = (long long)out_size;

    float* outp;
    float* attnp;
    if (os >= OUT_E + ATT_E) {
        outp  = (float*)d_out;
        attnp = (float*)d_out + OUT_E;
    } else if (os == ATT_E) {
        attnp = (float*)d_out;
        cudaGetSymbolAddress((void**)&outp, g_out_scratch);
    } else {
        outp = (float*)d_out;
        cudaGetSymbolAddress((void**)&attnp, g_attn_scratch);
    }

    cudaFuncSetAttribute(k_stats_tc, cudaFuncAttributeMaxDynamicSharedMemorySize, 2 * STATS_STG);
    cudaFuncSetAttribute(k_attnv_tc, cudaFuncAttributeMaxDynamicSharedMemorySize, 2 * AV2_STG);

    k_qkv<<<ROWSv / 64, 256>>>(x, Wq, Wk, Wv);
    k_stats_tc<<<dim3(16, 32), 256, 2 * STATS_STG>>>(attnp);
    k_attnv_tc<<<dim3(16, 32), 256, 2 * AV2_STG>>>(attnp);
    k_oproj_tc<<<dim3(8, 64), 256>>>(Wo, bo, outp);
}

// round 16
// speedup vs baseline: 1.2136x; 1.2136x over previous
#include <cuda_runtime.h>
#include <cuda_bf16.h>
#include <cstdint>

// Problem constants
#define Nn 4
#define Pp 2048
#define Dd 512
#define Hh 8
#define HDv 64
#define NHv (Nn*Hh)              // 32
#define ROWSv (Nn*Pp*Hh)         // 65536
#define SCALE 0.04419417382415922f   // 1/sqrt(512)

// ---------------------------------------------------------------------------
// Device scratch (no allocations allowed)
// ---------------------------------------------------------------------------
static __device__ __nv_bfloat16 g_qh[Nn*Pp*Dd];     // Q hi  [nh][p][64]
static __device__ __nv_bfloat16 g_ql[Nn*Pp*Dd];     // Q lo
static __device__ __nv_bfloat16 g_kh[Nn*Pp*Dd];     // K hi
static __device__ __nv_bfloat16 g_kl[Nn*Pp*Dd];     // K lo
static __device__ __nv_bfloat16 g_vTh[Nn*Pp*Dd];    // V^T hi [nh][e=64][p=2048]
static __device__ __nv_bfloat16 g_vTl[Nn*Pp*Dd];    // V^T lo
static __device__ uint32_t g_oh[Nn*Pp*Dd/2];        // O hi, bf16x2 [row(8192)][256]
static __device__ uint32_t g_ol[Nn*Pp*Dd/2];        // O lo
static __device__ float g_rowmax[ROWSv];
static __device__ float g_rowinv[ROWSv];
static __device__ float g_attn_scratch[NHv*Pp*Pp];   // fallback
static __device__ float g_out_scratch[Nn*Pp*Dd];     // fallback

// ---------------------------------------------------------------------------
// PTX helpers
// ---------------------------------------------------------------------------
__device__ __forceinline__ uint32_t s2u(const void* p) {
    uint32_t a;
    asm("{ .reg .u64 t; cvta.to.shared.u64 t, %1; cvt.u32.u64 %0, t; }"
        : "=r"(a) : "l"(p));
    return a;
}

__device__ __forceinline__ void mma_bf16(float* c, const uint32_t* a,
                                         const uint32_t* b) {
    asm volatile(
        "mma.sync.aligned.m16n8k16.row.col.f32.bf16.bf16.f32 "
        "{%0,%1,%2,%3}, {%4,%5,%6,%7}, {%8,%9}, {%0,%1,%2,%3};"
        : "+f"(c[0]), "+f"(c[1]), "+f"(c[2]), "+f"(c[3])
        : "r"(a[0]), "r"(a[1]), "r"(a[2]), "r"(a[3]),
          "r"(b[0]), "r"(b[1]));
}

__device__ __forceinline__ void ldsm_x4(uint32_t* r, uint32_t addr) {
    asm volatile(
        "ldmatrix.sync.aligned.m8n8.x4.shared.b16 {%0,%1,%2,%3}, [%4];"
        : "=r"(r[0]), "=r"(r[1]), "=r"(r[2]), "=r"(r[3]) : "r"(addr));
}

__device__ __forceinline__ void cpa16(uint32_t saddr, const void* gaddr) {
    asm volatile("cp.async.ca.shared.global [%0], [%1], 16;"
                 :: "r"(saddr), "l"(gaddr) : "memory");
}
#define CPA_COMMIT() asm volatile("cp.async.commit_group;" ::: "memory")
#define CPA_WAIT0()  asm volatile("cp.async.wait_group 0;" ::: "memory")
#define CPA_WAIT1()  asm volatile("cp.async.wait_group 1;" ::: "memory")

__device__ __forceinline__ uint32_t pack2bf(float a, float b) {
    __nv_bfloat162 t = __floats2bfloat162_rn(a, b);
    return *reinterpret_cast<uint32_t*>(&t);
}
__device__ __forceinline__ void packhilo(float a, float b,
                                         uint32_t& hi, uint32_t& lo) {
    float ha = __bfloat162float(__float2bfloat16_rn(a));
    float hb = __bfloat162float(__float2bfloat16_rn(b));
    hi = pack2bf(a, b);
    lo = pack2bf(a - ha, b - hb);
}
__device__ __forceinline__ void split4(float x0, float x1, float x2, float x3,
                                       uint2& hi, uint2& lo) {
    packhilo(x0, x1, hi.x, lo.x);
    packhilo(x2, x3, hi.y, lo.y);
}

#define FMA16(acc, a, b)                                     \
  acc[0][0] += a.x*b.x; acc[0][1] += a.x*b.y;                \
  acc[0][2] += a.x*b.z; acc[0][3] += a.x*b.w;                \
  acc[1][0] += a.y*b.x; acc[1][1] += a.y*b.y;                \
  acc[1][2] += a.y*b.z; acc[1][3] += a.y*b.w;                \
  acc[2][0] += a.z*b.x; acc[2][1] += a.z*b.y;                \
  acc[2][2] += a.z*b.z; acc[2][3] += a.z*b.w;                \
  acc[3][0] += a.w*b.x; acc[3][1] += a.w*b.y;                \
  acc[3][2] += a.w*b.z; acc[3][3] += a.w*b.w;

// ---------------------------------------------------------------------------
// K1: QKV projection (FFMA) -> bf16 hi/lo outputs; V transposed.
// ---------------------------------------------------------------------------
__global__ __launch_bounds__(256) void k_qkv(
    const float* __restrict__ x,
    const float* __restrict__ Wq, const float* __restrict__ Wk,
    const float* __restrict__ Wv)
{
    __shared__ __align__(16) float Xst[64][68];
    __shared__ __align__(16) float Wt[64][68];
    const int r0  = blockIdx.x * 64;
    const int tid = threadIdx.x;

    for (int i = tid; i < 4096; i += 256) {
        int r = i >> 6, d = i & 63;
        Xst[d][r] = x[(size_t)(r0 + r) * 64 + d];
    }

    const int tx = tid & 15, ty = tid >> 4;
    const float* Ws[3] = {Wq, Wk, Wv};

    for (int m = 0; m < 3; m++) {
        __syncthreads();
        for (int i = tid; i < 4096; i += 256) {
            int e = i >> 6, d = i & 63;
            Wt[d][e] = Ws[m][i];
        }
        __syncthreads();

        float acc[4][4] = {};
        #pragma unroll 8
        for (int d = 0; d < 64; d++) {
            float4 a = *(const float4*)&Xst[d][ty * 4];
            float4 b = *(const float4*)&Wt[d][tx * 4];
            FMA16(acc, a, b);
        }

        if (m < 2) {
            __nv_bfloat16* Gh = (m == 0) ? g_qh : g_kh;
            __nv_bfloat16* Gl = (m == 0) ? g_ql : g_kl;
            #pragma unroll
            for (int i2 = 0; i2 < 4; i2++) {
                int r = r0 + ty * 4 + i2;
                int h = r & 7; int np = r >> 3;
                int p = np & 2047; int n_ = np >> 11;
                size_t dst = ((size_t)((n_ * 8 + h) * 2048 + p)) * 64 + tx * 4;
                uint2 hi, lo;
                split4(acc[i2][0], acc[i2][1], acc[i2][2], acc[i2][3], hi, lo);
                *(uint2*)&Gh[dst] = hi;
                *(uint2*)&Gl[dst] = lo;
            }
        } else {
            __syncthreads();
            #pragma unroll
            for (int i2 = 0; i2 < 4; i2++)
                #pragma unroll
                for (int j = 0; j < 4; j++)
                    Xst[tx * 4 + j][ty * 4 + i2] = acc[i2][j];
            __syncthreads();

            int np0 = r0 >> 3;
            int n_ = np0 >> 11;
            int p0 = np0 & 2047;
            #pragma unroll
            for (int pr = 0; pr < 2; pr++) {
                int pair = tid + pr * 256;       // (h, e)
                int h = pair >> 6, e = pair & 63;
                float v[8];
                #pragma unroll
                for (int pi = 0; pi < 8; pi++) v[pi] = Xst[e][pi * 8 + h];
                uint2 hi0, lo0, hi1, lo1;
                split4(v[0], v[1], v[2], v[3], hi0, lo0);
                split4(v[4], v[5], v[6], v[7], hi1, lo1);
                uint4 hi4 = make_uint4(hi0.x, hi0.y, hi1.x, hi1.y);
                uint4 lo4 = make_uint4(lo0.x, lo0.y, lo1.x, lo1.y);
                size_t base = ((size_t)((n_ * 8 + h) * 64 + e)) * 2048 + p0;
                *(uint4*)&g_vTh[base] = hi4;
                *(uint4*)&g_vTl[base] = lo4;
            }
        }
    }
}

// ---------------------------------------------------------------------------
// K2: softmax row stats. E approx with SINGLE bf16 product (Qh*Kh) — stats
// errors average out in S; m is an arbitrary stable shift. Kh-only staging.
// grid = (qb=16, nh=32), 256 threads, 2 blocks/SM, cp.async 2-stage.
// ---------------------------------------------------------------------------
#define STATS_STG 18432
__global__ __launch_bounds__(256, 2) void k_stats_tc()
{
    extern __shared__ __align__(16) char dynsm[];
    const uint32_t smb = s2u(dynsm);

    const int tid = threadIdx.x;
    const int w = tid >> 5, lane = tid & 31;
    const int qb = blockIdx.x, nh = blockIdx.y;
    const int q0 = qb * 128;

    uint32_t aqh[16];
    {
        const uint32_t* qhp = (const uint32_t*)g_qh;
        int qrow = nh * 2048 + q0 + w * 16;
        #pragma unroll
        for (int dc = 0; dc < 4; dc++)
            #pragma unroll
            for (int r = 0; r < 4; r++) {
                int row = qrow + (lane >> 2) + 8 * (r & 1);
                int col2 = dc * 8 + (lane & 3) + 4 * (r >> 1);
                aqh[dc * 4 + r] = qhp[(size_t)row * 32 + col2];
            }
    }

    auto issue = [&](int st, int kc) {
        uint32_t sb = smb + st * STATS_STG;
        #pragma unroll
        for (int it = 0; it < 4; it++) {
            int idx = it * 256 + tid;
            int row = idx >> 3, c8 = idx & 7;
            cpa16(sb + (uint32_t)(row * 144 + c8 * 16),
                  (const uint4*)g_kh + (size_t)(nh * 2048 + kc + row) * 8 + c8);
        }
    };

    float m0 = -1e30f, s0 = 0.f, m1 = -1e30f, s1 = 0.f;

    issue(0, 0);
    CPA_COMMIT();

    for (int ic = 0; ic < 16; ic++) {
        if (ic + 1 < 16) {
            issue((ic + 1) & 1, (ic + 1) * 128);
            CPA_COMMIT();
            CPA_WAIT1();
        } else {
            CPA_WAIT0();
        }
        __syncthreads();

        const char* khp = dynsm + (ic & 1) * STATS_STG;

        #pragma unroll 4
        for (int n8 = 0; n8 < 16; n8++) {
            float c[4] = {0.f, 0.f, 0.f, 0.f};
            int tok = n8 * 8 + (lane >> 2);
            #pragma unroll
            for (int dc = 0; dc < 4; dc++) {
                int dcol = dc * 16 + (lane & 3) * 2;
                uint32_t bh[2];
                bh[0] = *(const uint32_t*)(khp + tok * 144 + dcol * 2);
                bh[1] = *(const uint32_t*)(khp + tok * 144 + dcol * 2 + 16);
                mma_bf16(c, &aqh[dc * 4], bh);
            }
            float e0 = c[0] * SCALE, e1 = c[1] * SCALE;
            float e2 = c[2] * SCALE, e3 = c[3] * SCALE;
            float lm0 = fmaxf(e0, e1), lm1 = fmaxf(e2, e3);
            float nm0 = fmaxf(m0, lm0), nm1 = fmaxf(m1, lm1);
            s0 = s0 * __expf(m0 - nm0) + __expf(e0 - nm0) + __expf(e1 - nm0);
            s1 = s1 * __expf(m1 - nm1) + __expf(e2 - nm1) + __expf(e3 - nm1);
            m0 = nm0; m1 = nm1;
        }
        __syncthreads();
    }

    #pragma unroll
    for (int off = 1; off <= 2; off <<= 1) {
        float om = __shfl_xor_sync(0xFFFFFFFFu, m0, off);
        float os = __shfl_xor_sync(0xFFFFFFFFu, s0, off);
        float nm = fmaxf(m0, om);
        s0 = s0 * __expf(m0 - nm) + os * __expf(om - nm);
        m0 = nm;
        om = __shfl_xor_sync(0xFFFFFFFFu, m1, off);
        os = __shfl_xor_sync(0xFFFFFFFFu, s1, off);
        nm = fmaxf(m1, om);
        s1 = s1 * __expf(m1 - nm) + os * __expf(om - nm);
        m1 = nm;
    }
    if ((lane & 3) == 0) {
        int grow0 = nh * 2048 + q0 + w * 16 + (lane >> 2);
        g_rowmax[grow0] = m0;
        g_rowinv[grow0] = 1.0f / s0;
        g_rowmax[grow0 + 8] = m1;
        g_rowinv[grow0 + 8] = 1.0f / s1;
    }
}

// ---------------------------------------------------------------------------
// K3: compute E (full 3-product), normalize -> write attention; chain P into
// A@V (3-product). grid = (qb=16, nh=32), 256 threads, 2 blocks/SM, cp.async.
// NOTE: here E uses the accurate 3-product form; S from stats is a sum whose
// per-term approximation errors average out, so softmax normalization holds.
// ---------------------------------------------------------------------------
#define AV_STG 36864
__global__ __launch_bounds__(256, 2) void k_attnv_tc(float* __restrict__ attn)
{
    extern __shared__ __align__(16) char dynsm[];
    const uint32_t smb = s2u(dynsm);

    const int tid = threadIdx.x;
    const int w = tid >> 5, lane = tid & 31;
    const int qb = blockIdx.x, nh = blockIdx.y;
    const int q0 = qb * 128;
    const int n_ = nh >> 3, h = nh & 7;

    uint32_t aqh[16], aql[16];
    {
        const uint32_t* qhp = (const uint32_t*)g_qh;
        const uint32_t* qlp = (const uint32_t*)g_ql;
        int qrow = nh * 2048 + q0 + w * 16;
        #pragma unroll
        for (int dc = 0; dc < 4; dc++)
            #pragma unroll
            for (int r = 0; r < 4; r++) {
                int row = qrow + (lane >> 2) + 8 * (r & 1);
                int col2 = dc * 8 + (lane & 3) + 4 * (r >> 1);
                aqh[dc * 4 + r] = qhp[(size_t)row * 32 + col2];
                aql[dc * 4 + r] = qlp[(size_t)row * 32 + col2];
            }
    }

    const int r0g = nh * 2048 + q0 + w * 16 + (lane >> 2);
    const float m0 = g_rowmax[r0g],     i0 = g_rowinv[r0g];
    const float m1 = g_rowmax[r0g + 8], i1 = g_rowinv[r0g + 8];

    float* arow0 = attn + (size_t)r0g * 2048;
    float* arow1 = attn + (size_t)(r0g + 8) * 2048;

    auto issue = [&](int st, int kc) {
        uint32_t sb = smb + st * AV_STG;
        #pragma unroll
        for (int it = 0; it < 2; it++) {
            int idx = it * 256 + tid;
            int row = idx >> 3, c8 = idx & 7;
            uint32_t so = sb + (uint32_t)(row * 144 + c8 * 16);
            cpa16(so,         (const uint4*)g_kh  + (size_t)(nh * 2048 + kc + row) * 8 + c8);
            cpa16(so + 9216,  (const uint4*)g_kl  + (size_t)(nh * 2048 + kc + row) * 8 + c8);
            cpa16(so + 18432, (const uint4*)g_vTh + (size_t)(nh * 64 + row) * 256 + (kc >> 3) + c8);
            cpa16(so + 27648, (const uint4*)g_vTl + (size_t)(nh * 64 + row) * 256 + (kc >> 3) + c8);
        }
    };

    float o[8][4];
    #pragma unroll
    for (int ne = 0; ne < 8; ne++)
        #pragma unroll
        for (int j = 0; j < 4; j++) o[ne][j] = 0.f;

    issue(0, 0);
    CPA_COMMIT();

    for (int ic = 0; ic < 32; ic++) {
        const int kc = ic * 64;
        if (ic + 1 < 32) {
            issue((ic + 1) & 1, kc + 64);
            CPA_COMMIT();
            CPA_WAIT1();
        } else {
            CPA_WAIT0();
        }
        __syncthreads();

        const char* khp = dynsm + (ic & 1) * AV_STG;
        const char* klp = khp + 9216;
        const char* vhp = khp + 18432;
        const char* vlp = khp + 27648;

        #pragma unroll
        for (int h2 = 0; h2 < 2; h2++) {
            uint32_t pah[8], pal[8];
            #pragma unroll
            for (int n8l = 0; n8l < 4; n8l++) {
                int n8 = h2 * 4 + n8l;
                float c[4] = {0.f, 0.f, 0.f, 0.f};
                int tok = n8 * 8 + (lane >> 2);
                #pragma unroll
                for (int dc = 0; dc < 4; dc++) {
                    int dcol = dc * 16 + (lane & 3) * 2;
                    uint32_t bh[2], bl[2];
                    bh[0] = *(const uint32_t*)(khp + tok * 144 + dcol * 2);
                    bh[1] = *(const uint32_t*)(khp + tok * 144 + dcol * 2 + 16);
                    bl[0] = *(const uint32_t*)(klp + tok * 144 + dcol * 2);
                    bl[1] = *(const uint32_t*)(klp + tok * 144 + dcol * 2 + 16);
                    mma_bf16(c, &aqh[dc * 4], bh);
                    mma_bf16(c, &aqh[dc * 4], bl);
                    mma_bf16(c, &aql[dc * 4], bh);
                }
                float p0 = __expf(c[0] * SCALE - m0) * i0;
                float p1 = __expf(c[1] * SCALE - m0) * i0;
                float p2 = __expf(c[2] * SCALE - m1) * i1;
                float p3 = __expf(c[3] * SCALE - m1) * i1;
                int col = kc + n8 * 8 + (lane & 3) * 2;
                *(float2*)&arow0[col] = make_float2(p0, p1);
                *(float2*)&arow1[col] = make_float2(p2, p3);
                int base = (n8l >> 1) * 4 + (n8l & 1) * 2;
                packhilo(p0, p1, pah[base],     pal[base]);
                packhilo(p2, p3, pah[base + 1], pal[base + 1]);
            }

            #pragma unroll
            for (int kkl = 0; kkl < 2; kkl++) {
                int kk = h2 * 2 + kkl;
                #pragma unroll
                for (int ne = 0; ne < 8; ne++) {
                    int e = ne * 8 + (lane >> 2);
                    int tcol = kk * 16 + (lane & 3) * 2;
                    uint32_t bh[2], bl[2];
                    bh[0] = *(const uint32_t*)(vhp + e * 144 + tcol * 2);
                    bh[1] = *(const uint32_t*)(vhp + e * 144 + tcol * 2 + 16);
                    bl[0] = *(const uint32_t*)(vlp + e * 144 + tcol * 2);
                    bl[1] = *(const uint32_t*)(vlp + e * 144 + tcol * 2 + 16);
                    mma_bf16(o[ne], &pah[kkl * 4], bh);
                    mma_bf16(o[ne], &pah[kkl * 4], bl);
                    mma_bf16(o[ne], &pal[kkl * 4], bh);
                }
            }
        }
        __syncthreads();
    }

    // epilogue: O rows as bf16 hi/lo (row-major [8192][256] words)
    int row = n_ * 2048 + q0 + w * 16 + (lane >> 2);
    #pragma unroll
    for (int ne = 0; ne < 8; ne++) {
        int col2 = h * 32 + ne * 4 + (lane & 3);
        uint32_t hh, ll;
        packhilo(o[ne][0], o[ne][1], hh, ll);
        g_oh[(size_t)row * 256 + col2] = hh;
        g_ol[(size_t)row * 256 + col2] = ll;
        packhilo(o[ne][2], o[ne][3], hh, ll);
        g_oh[(size_t)(row + 8) * 256 + col2] = hh;
        g_ol[(size_t)(row + 8) * 256 + col2] = ll;
    }
}

// ---------------------------------------------------------------------------
// K4: out = O @ Wo^T + bo via split bf16 HMMA. 2 blocks/SM.
// grid = (cb=8, rb=64), 256 threads (8 warps, 16 r-rows each).
// ---------------------------------------------------------------------------
__global__ __launch_bounds__(256, 2) void k_oproj_tc(
    const float* __restrict__ Wo, const float* __restrict__ bo,
    float* __restrict__ out)
{
    __shared__ __align__(16) __nv_bfloat16 Wh[64][72];
    __shared__ __align__(16) __nv_bfloat16 Wl[64][72];

    const int tid = threadIdx.x;
    const int w = tid >> 5, lane = tid & 31;
    const int c0 = blockIdx.x * 64, r0 = blockIdx.y * 128;

    const uint32_t whb = s2u(&Wh[0][0]);
    const uint32_t wlb = s2u(&Wl[0][0]);
    const uint32_t lmoff = (uint32_t)((lane & 7) * 144 + (lane >> 3) * 16);

    float acc[8][4];
    #pragma unroll
    for (int n8 = 0; n8 < 8; n8++)
        #pragma unroll
        for (int j = 0; j < 4; j++) acc[n8][j] = 0.f;

    for (int cc = 0; cc < 8; cc++) {
        if (cc) __syncthreads();
        #pragma unroll
        for (int it = 0; it < 8; it++) {
            int pi = it * 256 + tid;
            int row = pi >> 5, cp = pi & 31;
            float2 w2 = *(const float2*)&Wo[(size_t)(c0 + row) * 512 + cc * 64 + cp * 2];
            uint32_t hh, ll;
            packhilo(w2.x, w2.y, hh, ll);
            *(uint32_t*)&Wh[row][cp * 2] = hh;
            *(uint32_t*)&Wl[row][cp * 2] = ll;
        }
        __syncthreads();

        uint32_t aoh[16], aol[16];
        int rrow = r0 + w * 16;
        #pragma unroll
        for (int dc = 0; dc < 4; dc++)
            #pragma unroll
            for (int r = 0; r < 4; r++) {
                int row = rrow + (lane >> 2) + 8 * (r & 1);
                int col2 = cc * 32 + dc * 8 + (lane & 3) + 4 * (r >> 1);
                aoh[dc * 4 + r] = g_oh[(size_t)row * 256 + col2];
                aol[dc * 4 + r] = g_ol[(size_t)row * 256 + col2];
            }

        #pragma unroll
        for (int n8 = 0; n8 < 8; n8++) {
            uint32_t bh[8], bl[8];
            uint32_t base = (uint32_t)(n8 * 1152) + lmoff;
            ldsm_x4(bh,     whb + base);
            ldsm_x4(bh + 4, whb + base + 64);
            ldsm_x4(bl,     wlb + base);
            ldsm_x4(bl + 4, wlb + base + 64);
            #pragma unroll
            for (int dc = 0; dc < 4; dc++) {
                mma_bf16(acc[n8], &aoh[dc * 4], &bh[dc * 2]);
                mma_bf16(acc[n8], &aoh[dc * 4], &bl[dc * 2]);
                mma_bf16(acc[n8], &aol[dc * 4], &bh[dc * 2]);
            }
        }
    }

    int row = r0 + w * 16 + (lane >> 2);
    #pragma unroll
    for (int n8 = 0; n8 < 8; n8++) {
        int c = c0 + n8 * 8 + (lane & 3) * 2;
        float2 bb = *(const float2*)&bo[c];
        *(float2*)&out[(size_t)row * 512 + c] =
            make_float2(acc[n8][0] + bb.x, acc[n8][1] + bb.y);
        *(float2*)&out[(size_t)(row + 8) * 512 + c] =
            make_float2(acc[n8][2] + bb.x, acc[n8][3] + bb.y);
    }
}

// ---------------------------------------------------------------------------
extern "C" void kernel_launch(void* const* d_in, const int* in_sizes, int n_in,
                              void* d_out, int out_size)
{
    const float* x  = (const float*)d_in[0];
    const float* Wq = (const float*)d_in[1];
    const float* Wk = (const float*)d_in[2];
    const float* Wv = (const float*)d_in[3];
    const float* Wo = (const float*)d_in[4];
    const float* bo = (const float*)d_in[5];

    const long long OUT_E = (long long)Nn * Pp * Dd;      // 4194304
    const long long ATT_E = (long long)NHv * Pp * Pp;     // 134217728
    const long long os = (long long)out_size;

    float* outp;
    float* attnp;
    if (os >= OUT_E + ATT_E) {
        outp  = (float*)d_out;
        attnp = (float*)d_out + OUT_E;
    } else if (os == ATT_E) {
        attnp = (float*)d_out;
        cudaGetSymbolAddress((void**)&outp, g_out_scratch);
    } else {
        outp = (float*)d_out;
        cudaGetSymbolAddress((void**)&attnp, g_attn_scratch);
    }

    cudaFuncSetAttribute(k_stats_tc, cudaFuncAttributeMaxDynamicSharedMemorySize, 2 * STATS_STG);
    cudaFuncSetAttribute(k_attnv_tc, cudaFuncAttributeMaxDynamicSharedMemorySize, 2 * AV_STG);

    k_qkv<<<ROWSv / 64, 256>>>(x, Wq, Wk, Wv);
    k_stats_tc<<<dim3(16, 32), 256, 2 * STATS_STG>>>();
    k_attnv_tc<<<dim3(16, 32), 256, 2 * AV_STG>>>(attnp);
    k_oproj_tc<<<dim3(8, 64), 256>>>(Wo, bo, outp);
}